// round 1
// baseline (speedup 1.0000x reference)
#include <cuda_runtime.h>
#include <cuda_bf16.h>

// Problem constants (fixed by the reference setup)
#define N_BATCH   256
#define SIG       10
#define NB_CHROM  23
#define NB_GENES  20000
#define HIDDEN    32
#define BN_EPS    1e-5f

// Scratch: batch-normalized activations h_bn[n][c], (256 x 23)
__device__ float g_hbn[N_BATCH * NB_CHROM];

// ---------------------------------------------------------------------------
// Kernel 1: h = relu(x @ lin_w^T + lin_b); BN over batch (biased var, training
// mode); write h_bn to g_hbn. One block, 256 threads (thread = batch row).
// ---------------------------------------------------------------------------
__global__ void __launch_bounds__(N_BATCH)
k1_base_block(const float* __restrict__ x,
              const float* __restrict__ lin_w,
              const float* __restrict__ lin_b,
              const float* __restrict__ bn_gamma,
              const float* __restrict__ bn_beta)
{
    __shared__ float sh_w[NB_CHROM * SIG];
    __shared__ float sh_b[NB_CHROM];
    __shared__ float sh_h[N_BATCH * NB_CHROM];
    __shared__ float sh_scale[NB_CHROM];
    __shared__ float sh_shift[NB_CHROM];

    const int t = threadIdx.x;
    if (t < NB_CHROM * SIG) sh_w[t] = lin_w[t];
    if (t < NB_CHROM)       sh_b[t] = lin_b[t];
    __syncthreads();

    // each thread = one batch row
    float xr[SIG];
#pragma unroll
    for (int i = 0; i < SIG; i++) xr[i] = x[t * SIG + i];

#pragma unroll
    for (int c = 0; c < NB_CHROM; c++) {
        float acc = sh_b[c];
#pragma unroll
        for (int i = 0; i < SIG; i++) acc = fmaf(xr[i], sh_w[c * SIG + i], acc);
        sh_h[t * NB_CHROM + c] = fmaxf(acc, 0.0f);
    }
    __syncthreads();

    // Deterministic per-channel batch stats: thread c sums over 256 rows.
    if (t < NB_CHROM) {
        float s = 0.0f, sq = 0.0f;
#pragma unroll 8
        for (int n = 0; n < N_BATCH; n++) {
            float v = sh_h[n * NB_CHROM + t];
            s  += v;
            sq += v * v;
        }
        float mu  = s * (1.0f / N_BATCH);
        float var = sq * (1.0f / N_BATCH) - mu * mu;   // biased (torch BN)
        float inv = rsqrtf(var + BN_EPS);
        float g   = bn_gamma[t];
        sh_scale[t] = inv * g;
        sh_shift[t] = bn_beta[t] - mu * inv * g;
    }
    __syncthreads();

#pragma unroll
    for (int c = 0; c < NB_CHROM; c++)
        g_hbn[t * NB_CHROM + c] =
            fmaf(sh_h[t * NB_CHROM + c], sh_scale[c], sh_shift[c]);
}

// ---------------------------------------------------------------------------
// Kernel 2: out[n,g,f] = s[n,g]*conv_w[f] + r[g]*conv_b[f]
//   s[n,g] = sum_c gene_w[g,c] * h_bn[n,c],  r[g] = sum_c gene_w[g,c]
// Tile: 128 genes (blockIdx.x) x 16 batch rows (blockIdx.y), 256 threads.
// ---------------------------------------------------------------------------
#define GT 128   // genes per tile
#define NT 16    // batch rows per tile
#define TPB 256

__global__ void __launch_bounds__(TPB)
k2_decode(const float* __restrict__ gene_w,
          const float* __restrict__ conv_w,
          const float* __restrict__ conv_b,
          float* __restrict__ out)
{
    __shared__ float  sh_gw[GT * NB_CHROM];   // 11776 B (stride 23: odd -> conflict-free)
    __shared__ float  sh_a[NT * NB_CHROM];    // 1472 B
    __shared__ float  sh_s[NT * GT];          // 8192 B
    __shared__ float  sh_r[GT];               // 512 B
    __shared__ float4 sh_cw[HIDDEN / 4];      // 128 B
    __shared__ float4 sh_cb[HIDDEN / 4];      // 128 B

    const int t  = threadIdx.x;
    const int g0 = blockIdx.x * GT;
    const int n0 = blockIdx.y * NT;
    const int gcount = min(GT, NB_GENES - g0);

    // ---- loads ----
    for (int i = t; i < gcount * NB_CHROM; i += TPB)
        sh_gw[i] = gene_w[g0 * NB_CHROM + i];
    for (int i = t; i < NT * NB_CHROM; i += TPB)
        sh_a[i] = g_hbn[n0 * NB_CHROM + i];
    if (t < HIDDEN / 4) {
        sh_cw[t] = reinterpret_cast<const float4*>(conv_w)[t];
        sh_cb[t] = reinterpret_cast<const float4*>(conv_b)[t];
    }
    __syncthreads();

    // ---- per-gene row-sum r[g] ----
    if (t < GT) {
        float r = 0.0f;
        if (t < gcount) {
#pragma unroll
            for (int c = 0; c < NB_CHROM; c++) r += sh_gw[t * NB_CHROM + c];
        }
        sh_r[t] = r;
    }

    // ---- s[n,g] dots (length-23) ----
    for (int p = t; p < NT * GT; p += TPB) {
        const int nl = p >> 7;        // p / GT
        const int gl = p & (GT - 1);  // p % GT
        float acc = 0.0f;
        if (gl < gcount) {
#pragma unroll
            for (int c = 0; c < NB_CHROM; c++)
                acc = fmaf(sh_gw[gl * NB_CHROM + c], sh_a[nl * NB_CHROM + c], acc);
        }
        sh_s[p] = acc;
    }
    __syncthreads();

    // ---- streamed coalesced output: 128B per (n,g), float4 granularity ----
    // j = t + k*TPB keeps j%8 == t%8, so each thread's f-quad is fixed.
    const int f4 = t & 7;
    const float4 cw4 = sh_cw[f4];
    const float4 cb4 = sh_cb[f4];
    float4* __restrict__ o4 = reinterpret_cast<float4*>(out);

    const int jmax = gcount * (HIDDEN / 4);   // float4s per n-row of this tile
#pragma unroll 1
    for (int nl = 0; nl < NT; nl++) {
        const size_t base4 =
            ((size_t)(n0 + nl) * NB_GENES + (size_t)g0) * (HIDDEN / 4);
        const float* __restrict__ srow = &sh_s[nl * GT];
#pragma unroll 4
        for (int j = t; j < jmax; j += TPB) {
            const int gl = j >> 3;
            const float s = srow[gl];
            const float r = sh_r[gl];
            float4 v;
            v.x = fmaf(s, cw4.x, r * cb4.x);
            v.y = fmaf(s, cw4.y, r * cb4.y);
            v.z = fmaf(s, cw4.z, r * cb4.z);
            v.w = fmaf(s, cw4.w, r * cb4.w);
            o4[base4 + (size_t)j] = v;
        }
    }
}

// ---------------------------------------------------------------------------
// Launch
// ---------------------------------------------------------------------------
extern "C" void kernel_launch(void* const* d_in, const int* in_sizes, int n_in,
                              void* d_out, int out_size)
{
    const float* x        = (const float*)d_in[0];
    const float* lin_w    = (const float*)d_in[1];
    const float* lin_b    = (const float*)d_in[2];
    const float* bn_gamma = (const float*)d_in[3];
    const float* bn_beta  = (const float*)d_in[4];
    const float* conv_w   = (const float*)d_in[5];
    const float* conv_b   = (const float*)d_in[6];
    const float* gene_w   = (const float*)d_in[7];
    // d_in[8] = mask; mask == (gene_w != 0) so gene_w*mask == gene_w — unused.

    k1_base_block<<<1, N_BATCH>>>(x, lin_w, lin_b, bn_gamma, bn_beta);

    dim3 grid((NB_GENES + GT - 1) / GT, N_BATCH / NT);
    k2_decode<<<grid, TPB>>>(gene_w, conv_w, conv_b, (float*)d_out);
}